// round 4
// baseline (speedup 1.0000x reference)
#include <cuda_runtime.h>
#include <cstdint>

#define B_     4
#define T_     400
#define U_     64
#define E_     320
#define INNER_ 512
#define VOCAB_ 1024

// Scratch (device globals: allowed; no runtime allocation)
__device__ float g_encp[B_ * T_ * INNER_];   // enc_proj, no bias
__device__ float g_decp[B_ * U_ * INNER_];   // dec_proj + b1 folded in

// ---------------------------------------------------------------------------
// packed f32x2 helpers (sm_103a paired-FMA path; only reachable via PTX)
// ---------------------------------------------------------------------------
__device__ __forceinline__ unsigned long long pack2(float lo, float hi) {
    unsigned long long r;
    asm("mov.b64 %0, {%1, %2};" : "=l"(r) : "f"(lo), "f"(hi));
    return r;
}
__device__ __forceinline__ unsigned long long fma2(unsigned long long a,
                                                   unsigned long long b,
                                                   unsigned long long c) {
    unsigned long long d;
    asm("fma.rn.f32x2 %0, %1, %2, %3;" : "=l"(d) : "l"(a), "l"(b), "l"(c));
    return d;
}
__device__ __forceinline__ void unpack2(unsigned long long v, float& lo, float& hi) {
    asm("mov.b64 {%0, %1}, %2;" : "=f"(lo), "=f"(hi) : "l"(v));
}
__device__ __forceinline__ float tanh_approx(float x) {
    float y;
    asm("tanh.approx.f32 %0, %1;" : "=f"(y) : "f"(x));
    return y;
}

// ---------------------------------------------------------------------------
// Kernel 1: projection GEMM.  C[m][i] = sum_k A[m][k] * W1[i][koff+k] (+b1[i])
// A: (M, 320) row-major.  W1: (512, 640) row-major.  Tiles: 64x64x16, 256 thr.
// Grid covers M exactly (1600 = 25*64 for enc, 256 = 4*64 for dec).
// ---------------------------------------------------------------------------
__global__ __launch_bounds__(256)
void proj_kernel(const float* __restrict__ A, const float* __restrict__ W1,
                 const float* __restrict__ b1, int isDec)
{
    __shared__ float As[16][64];
    __shared__ float Ws[16][68];

    const int tid  = threadIdx.x;
    const int m0   = blockIdx.x * 64;
    const int n0   = blockIdx.y * 64;
    const int koff = isDec ? E_ : 0;

    float acc[4][4] = {};

    for (int k0 = 0; k0 < E_; k0 += 16) {
        #pragma unroll
        for (int i = tid; i < 64 * 16; i += 256) {
            int r = i >> 4, k = i & 15;
            As[k][r] = A[(m0 + r) * E_ + k0 + k];
        }
        #pragma unroll
        for (int i = tid; i < 64 * 16; i += 256) {
            int c = i >> 4, k = i & 15;
            Ws[k][c] = W1[(n0 + c) * (2 * E_) + koff + k0 + k];
        }
        __syncthreads();

        const int ty = tid >> 4, tx = tid & 15;
        #pragma unroll
        for (int k = 0; k < 16; k++) {
            float a[4], w[4];
            #pragma unroll
            for (int i = 0; i < 4; i++) a[i] = As[k][ty * 4 + i];
            #pragma unroll
            for (int j = 0; j < 4; j++) w[j] = Ws[k][tx * 4 + j];
            #pragma unroll
            for (int i = 0; i < 4; i++)
                #pragma unroll
                for (int j = 0; j < 4; j++)
                    acc[i][j] = fmaf(a[i], w[j], acc[i][j]);
        }
        __syncthreads();
    }

    const int ty = tid >> 4, tx = tid & 15;
    float* C = isDec ? g_decp : g_encp;
    #pragma unroll
    for (int i = 0; i < 4; i++) {
        #pragma unroll
        for (int j = 0; j < 4; j++) {
            float v = acc[i][j];
            if (isDec) v += b1[n0 + tx * 4 + j];
            C[(m0 + ty * 4 + i) * INNER_ + n0 + tx * 4 + j] = v;
        }
    }
}

// ---------------------------------------------------------------------------
// Kernel 2: fused  out[b,t,u,v] = tanh(encp[b,t,:] + decp[b,u,:]) . W2[v,:] + b2[v]
// Block tile: rows = 16t x 8u = 128, cols = 128 vocab, K-chunks of 16.
// A-tile is generated on the fly: tiny (16+8)x16 global loads + tanh.approx.
// Inner product uses paired fp32 (fma.f32x2) -> 128 FMA-lanes/SM/cyc.
// Grid: x = VOCAB/128 = 8, y = (T/16)*(U/8) = 200, z = B = 4.
// Shared rows padded to 132 floats to rotate banks on the k-major
// transpose-store (stride 128 == 0 mod 32 was a 4-way write conflict).
// ---------------------------------------------------------------------------
#define HPAD 132

__global__ __launch_bounds__(256)
void main_kernel(const float* __restrict__ W2, const float* __restrict__ b2,
                 float* __restrict__ out)
{
    __shared__ __align__(16) float hs[16][HPAD];  // tanh rows, k-major
    __shared__ __align__(16) float ws[16][HPAD];  // W2 chunk, k-major
    __shared__ float es[16][16];                  // enc chunk [t][k]
    __shared__ float ds[8][16];                   // dec chunk [u][k]

    const int tid = threadIdx.x;
    const int b   = blockIdx.z;
    const int t0  = (blockIdx.y >> 3) * 16;
    const int u0  = (blockIdx.y & 7) * 8;
    const int v0  = blockIdx.x * 128;

    const float* eb = g_encp + (b * T_ + t0) * INNER_;
    const float* db = g_decp + (b * U_ + u0) * INNER_;

    const int ty = tid >> 4;       // 0..15 -> row group (fixed t)
    const int tx = tid & 15;       // 0..15 -> col group

    // acc2[i2][j]: rows (ty*8 + 2*i2, +1), col tx*8 + j, packed in f32x2
    unsigned long long acc2[4][8] = {};

    for (int k0 = 0; k0 < INNER_; k0 += 16) {
        // ---- stage raw chunks ----
        {
            int r = tid >> 4, k = tid & 15;
            es[r][k] = eb[r * INNER_ + k0 + k];
            if (tid < 128) {
                int ru = tid >> 4, ku = tid & 15;
                ds[ru][ku] = db[ru * INNER_ + k0 + ku];
            }
        }
        // W2 chunk: 128 v x 16 k, transpose-store into ws[k][v]
        #pragma unroll
        for (int i = tid; i < 128 * 16 / 4; i += 256) {
            int v  = i >> 2;
            int k4 = (i & 3) * 4;
            float4 w = *(const float4*)&W2[(v0 + v) * INNER_ + k0 + k4];
            ws[k4 + 0][v] = w.x;
            ws[k4 + 1][v] = w.y;
            ws[k4 + 2][v] = w.z;
            ws[k4 + 3][v] = w.w;
        }
        __syncthreads();

        // ---- build h tile: hs[k][tt*8+uu] = tanh(enc + dec) ----
        {
            int k  = tid >> 4;       // 0..15
            int tt = tid & 15;       // 0..15
            float ev = es[tt][k];
            #pragma unroll
            for (int uu = 0; uu < 8; uu++)
                hs[k][tt * 8 + uu] = tanh_approx(ev + ds[uu][k]);
        }
        __syncthreads();

        // ---- 128x128x16 MMA with fma.f32x2 ----
        #pragma unroll
        for (int k = 0; k < 16; k++) {
            ulonglong2 a01 = *(const ulonglong2*)&hs[k][ty * 8];      // row pairs
            ulonglong2 a23 = *(const ulonglong2*)&hs[k][ty * 8 + 4];
            float4 wA = *(const float4*)&ws[k][tx * 8];
            float4 wB = *(const float4*)&ws[k][tx * 8 + 4];
            unsigned long long av[4] = {a01.x, a01.y, a23.x, a23.y};
            unsigned long long bd[8];
            bd[0] = pack2(wA.x, wA.x); bd[1] = pack2(wA.y, wA.y);
            bd[2] = pack2(wA.z, wA.z); bd[3] = pack2(wA.w, wA.w);
            bd[4] = pack2(wB.x, wB.x); bd[5] = pack2(wB.y, wB.y);
            bd[6] = pack2(wB.z, wB.z); bd[7] = pack2(wB.w, wB.w);
            #pragma unroll
            for (int i2 = 0; i2 < 4; i2++)
                #pragma unroll
                for (int j = 0; j < 8; j++)
                    acc2[i2][j] = fma2(av[i2], bd[j], acc2[i2][j]);
        }
        __syncthreads();
    }

    // ---- epilogue: unpack, +b2, store ----
    float cr[8][8];
    #pragma unroll
    for (int i2 = 0; i2 < 4; i2++)
        #pragma unroll
        for (int j = 0; j < 8; j++)
            unpack2(acc2[i2][j], cr[2 * i2][j], cr[2 * i2 + 1][j]);

    float bias[8];
    #pragma unroll
    for (int j = 0; j < 8; j++) bias[j] = b2[v0 + tx * 8 + j];

    // thread's 8 rows: t = t0 + ty (fixed), u = u0 + rr
    float* obase = out + ((size_t)((b * T_ + t0 + ty) * U_ + u0)) * VOCAB_ + v0 + tx * 8;
    #pragma unroll
    for (int rr = 0; rr < 8; rr++) {
        float4 s0, s1;
        s0.x = cr[rr][0] + bias[0]; s0.y = cr[rr][1] + bias[1];
        s0.z = cr[rr][2] + bias[2]; s0.w = cr[rr][3] + bias[3];
        s1.x = cr[rr][4] + bias[4]; s1.y = cr[rr][5] + bias[5];
        s1.z = cr[rr][6] + bias[6]; s1.w = cr[rr][7] + bias[7];
        *(float4*)(obase + (size_t)rr * VOCAB_)     = s0;
        *(float4*)(obase + (size_t)rr * VOCAB_ + 4) = s1;
    }
}

// ---------------------------------------------------------------------------
extern "C" void kernel_launch(void* const* d_in, const int* in_sizes, int n_in,
                              void* d_out, int out_size)
{
    const float* enc = (const float*)d_in[0];   // (4,400,320)
    const float* dec = (const float*)d_in[1];   // (4,64,320)
    const float* W1  = (const float*)d_in[2];   // (512,640)
    const float* b1  = (const float*)d_in[3];   // (512,)
    const float* W2  = (const float*)d_in[4];   // (1024,512)
    const float* b2  = (const float*)d_in[5];   // (1024,)
    float* out = (float*)d_out;                 // (4,400,64,1024) f32

    proj_kernel<<<dim3(25, 8), 256>>>(enc, W1, b1, 0);   // 1600x512
    proj_kernel<<<dim3(4, 8),  256>>>(dec, W1, b1, 1);   // 256x512 (+b1)
    main_kernel<<<dim3(8, 200, 4), 256>>>(W2, b2, out);
}

// round 6
// speedup vs baseline: 4.1029x; 4.1029x over previous
#include <cuda_runtime.h>
#include <cuda_fp16.h>
#include <cstdint>

#define B_     4
#define T_     400
#define U_     64
#define E_     320
#define INNER_ 512
#define VOCAB_ 1024

// ---------------------------------------------------------------------------
// Device-global scratch (no runtime allocation allowed)
// ---------------------------------------------------------------------------
__device__ float  g_encp[B_ * T_ * INNER_];   // enc @ W1[:, :E]
__device__ float  g_decp[B_ * U_ * INNER_];   // dec @ W1[:, E:] + b1
__device__ __half g_w2f[VOCAB_ * INNER_];     // W2 in fp16 (rn)

__device__ __forceinline__ float tanh_approx(float x) {
    float y; asm("tanh.approx.f32 %0, %1;" : "=f"(y) : "f"(x)); return y;
}

// ---------------------------------------------------------------------------
// Kernel 1: projection GEMM (unchanged from R4 passing kernel)
// ---------------------------------------------------------------------------
__global__ __launch_bounds__(256)
void proj_kernel(const float* __restrict__ A, const float* __restrict__ W1,
                 const float* __restrict__ b1, int isDec)
{
    __shared__ float As[16][64];
    __shared__ float Ws[16][68];

    const int tid  = threadIdx.x;
    const int m0   = blockIdx.x * 64;
    const int n0   = blockIdx.y * 64;
    const int koff = isDec ? E_ : 0;

    float acc[4][4] = {};

    for (int k0 = 0; k0 < E_; k0 += 16) {
        #pragma unroll
        for (int i = tid; i < 64 * 16; i += 256) {
            int r = i >> 4, k = i & 15;
            As[k][r] = A[(m0 + r) * E_ + k0 + k];
        }
        #pragma unroll
        for (int i = tid; i < 64 * 16; i += 256) {
            int c = i >> 4, k = i & 15;
            Ws[k][c] = W1[(n0 + c) * (2 * E_) + koff + k0 + k];
        }
        __syncthreads();

        const int ty = tid >> 4, tx = tid & 15;
        #pragma unroll
        for (int k = 0; k < 16; k++) {
            float a[4], w[4];
            #pragma unroll
            for (int i = 0; i < 4; i++) a[i] = As[k][ty * 4 + i];
            #pragma unroll
            for (int j = 0; j < 4; j++) w[j] = Ws[k][tx * 4 + j];
            #pragma unroll
            for (int i = 0; i < 4; i++)
                #pragma unroll
                for (int j = 0; j < 4; j++)
                    acc[i][j] = fmaf(a[i], w[j], acc[i][j]);
        }
        __syncthreads();
    }

    const int ty = tid >> 4, tx = tid & 15;
    float* C = isDec ? g_decp : g_encp;
    #pragma unroll
    for (int i = 0; i < 4; i++)
        #pragma unroll
        for (int j = 0; j < 4; j++) {
            float v = acc[i][j];
            if (isDec) v += b1[n0 + tx * 4 + j];
            C[(m0 + ty * 4 + i) * INNER_ + n0 + tx * 4 + j] = v;
        }
}

// ---------------------------------------------------------------------------
// Kernel 2: W2 fp32 -> fp16 (one-time, 0.5M elems)
// ---------------------------------------------------------------------------
__global__ __launch_bounds__(256)
void w2half_kernel(const float* __restrict__ W2)
{
    int i = blockIdx.x * 256 + threadIdx.x;
    if (i < VOCAB_ * INNER_) g_w2f[i] = __float2half_rn(W2[i]);
}

// ---------------------------------------------------------------------------
// Kernel 3: fused tile kernel with mma.sync (HMMA fallback path).
//   Tile: 128 rows (16t x 8u) x 128 vocab, K-chunks of 64 (8 chunks).
//   8 warps in 2(m) x 4(n): each warp 64x32 via m16n8k16 fp16->f32.
//   A (h=tanh(enc+dec)) generated on the fly, stored fp16 in SMEM.
//   Rows padded to 72 fp16 (144B) -> all fragment LDS conflict-free.
// ---------------------------------------------------------------------------
#define APAD 72

__global__ __launch_bounds__(256, 2)
void main_mma_kernel(const float* __restrict__ b2, float* __restrict__ out)
{
    __shared__ float  es[16][68];
    __shared__ float  ds[8][68];
    __shared__ __half Ash[128][APAD];
    __shared__ __half Bsh[128][APAD];
    __shared__ float  bias_s[128];

    const int tid  = threadIdx.x;
    const int wid  = tid >> 5;
    const int lane = tid & 31;

    const int b  = blockIdx.z;
    const int t0 = (blockIdx.y >> 3) * 16;
    const int u0 = (blockIdx.y & 7) * 8;
    const int v0 = blockIdx.x * 128;

    const int warp_m = wid >> 2;          // 0..1 : rows warp_m*64
    const int warp_n = wid & 3;           // 0..3 : cols warp_n*32

    const float* eb = g_encp + (b * T_ + t0) * INNER_;
    const float* db = g_decp + (b * U_ + u0) * INNER_;

    if (tid < 128) bias_s[tid] = b2[v0 + tid];

    float acc[4][4][4] = {};              // [mtile][ntile][4]

    const int g   = lane >> 2;            // 0..7
    const int lq  = lane & 3;             // 0..3
    const int klo = lq * 2;

    for (int c = 0; c < 8; c++) {
        __syncthreads();   // previous chunk's MMA reads done before overwrite

        // ---- stage proj chunks (fp32) ----
        {
            int r = tid >> 4, k = (tid & 15) * 4;
            float4 v = *(const float4*)(eb + r * INNER_ + c * 64 + k);
            *(float4*)&es[r][k] = v;
            if (tid < 128) {
                int r2 = tid >> 4, k2 = (tid & 15) * 4;
                float4 w = *(const float4*)(db + r2 * INNER_ + c * 64 + k2);
                *(float4*)&ds[r2][k2] = w;
            }
        }
        // ---- stage B tile: 128 v x 64 k fp16 (uint4 = 8 fp16) ----
        {
            #pragma unroll
            for (int it = 0; it < 4; it++) {
                int idx = it * 256 + tid;
                int v   = idx >> 3;
                int seg = idx & 7;
                uint4 x = *(const uint4*)(g_w2f + (size_t)(v0 + v) * INNER_ + c * 64 + seg * 8);
                *(uint4*)&Bsh[v][seg * 8] = x;
            }
        }
        __syncthreads();

        // ---- build h tile: tanh(enc+dec) -> fp16 ----
        {
            int r  = tid >> 1;            // 0..127
            int kh = (tid & 1) * 32;
            int tt = r >> 3, uu = r & 7;
            #pragma unroll
            for (int k4 = 0; k4 < 32; k4 += 4) {
                float h0 = tanh_approx(es[tt][kh + k4 + 0] + ds[uu][kh + k4 + 0]);
                float h1 = tanh_approx(es[tt][kh + k4 + 1] + ds[uu][kh + k4 + 1]);
                float h2 = tanh_approx(es[tt][kh + k4 + 2] + ds[uu][kh + k4 + 2]);
                float h3 = tanh_approx(es[tt][kh + k4 + 3] + ds[uu][kh + k4 + 3]);
                __half2 p0 = __floats2half2_rn(h0, h1);
                __half2 p1 = __floats2half2_rn(h2, h3);
                uint2 pk;
                pk.x = *reinterpret_cast<uint32_t*>(&p0);
                pk.y = *reinterpret_cast<uint32_t*>(&p1);
                *(uint2*)&Ash[r][kh + k4] = pk;
            }
        }
        __syncthreads();

        // ---- MMA: 4 k-steps of 16 ----
        #pragma unroll
        for (int ks = 0; ks < 4; ks++) {
            const int kb = ks * 16;
            uint32_t af[4][4];
            #pragma unroll
            for (int mt = 0; mt < 4; mt++) {
                const int rb = warp_m * 64 + mt * 16;
                af[mt][0] = *(const uint32_t*)&Ash[rb + g    ][kb + klo    ];
                af[mt][1] = *(const uint32_t*)&Ash[rb + g + 8][kb + klo    ];
                af[mt][2] = *(const uint32_t*)&Ash[rb + g    ][kb + klo + 8];
                af[mt][3] = *(const uint32_t*)&Ash[rb + g + 8][kb + klo + 8];
            }
            uint32_t bf[4][2];
            #pragma unroll
            for (int nt = 0; nt < 4; nt++) {
                const int nb = warp_n * 32 + nt * 8;
                bf[nt][0] = *(const uint32_t*)&Bsh[nb + g][kb + klo    ];
                bf[nt][1] = *(const uint32_t*)&Bsh[nb + g][kb + klo + 8];
            }
            #pragma unroll
            for (int mt = 0; mt < 4; mt++)
                #pragma unroll
                for (int nt = 0; nt < 4; nt++) {
                    asm volatile(
                        "mma.sync.aligned.m16n8k16.row.col.f32.f16.f16.f32 "
                        "{%0,%1,%2,%3}, {%4,%5,%6,%7}, {%8,%9}, {%0,%1,%2,%3};"
                        : "+f"(acc[mt][nt][0]), "+f"(acc[mt][nt][1]),
                          "+f"(acc[mt][nt][2]), "+f"(acc[mt][nt][3])
                        : "r"(af[mt][0]), "r"(af[mt][1]), "r"(af[mt][2]), "r"(af[mt][3]),
                          "r"(bf[nt][0]), "r"(bf[nt][1]));
                }
        }
    }
    __syncthreads();

    // ---- epilogue: +bias, store fp32 ----
    #pragma unroll
    for (int mt = 0; mt < 4; mt++) {
        const int rb = warp_m * 64 + mt * 16;
        #pragma unroll
        for (int half = 0; half < 2; half++) {
            const int r  = rb + g + half * 8;
            const int tt = r >> 3, uu = r & 7;
            float* op = out + ((size_t)((b * T_ + t0 + tt) * U_ + u0 + uu)) * VOCAB_ + v0;
            #pragma unroll
            for (int nt = 0; nt < 4; nt++) {
                const int col = warp_n * 32 + nt * 8 + klo;
                float2 s;
                s.x = acc[mt][nt][half * 2 + 0] + bias_s[col + 0];
                s.y = acc[mt][nt][half * 2 + 1] + bias_s[col + 1];
                *(float2*)(op + col) = s;
            }
        }
    }
}

// ---------------------------------------------------------------------------
extern "C" void kernel_launch(void* const* d_in, const int* in_sizes, int n_in,
                              void* d_out, int out_size)
{
    const float* enc = (const float*)d_in[0];   // (4,400,320)
    const float* dec = (const float*)d_in[1];   // (4,64,320)
    const float* W1  = (const float*)d_in[2];   // (512,640)
    const float* b1  = (const float*)d_in[3];   // (512,)
    const float* W2  = (const float*)d_in[4];   // (1024,512)
    const float* b2  = (const float*)d_in[5];   // (1024,)
    float* out = (float*)d_out;                 // (4,400,64,1024) f32

    proj_kernel<<<dim3(25, 8), 256>>>(enc, W1, b1, 0);
    proj_kernel<<<dim3(4, 8),  256>>>(dec, W1, b1, 1);
    w2half_kernel<<<(VOCAB_ * INNER_ + 255) / 256, 256>>>(W2);
    main_mma_kernel<<<dim3(8, 200, 4), 256>>>(b2, out);
}

// round 7
// speedup vs baseline: 4.3180x; 1.0524x over previous
#include <cuda_runtime.h>
#include <cuda_fp16.h>
#include <cstdint>

#define B_     4
#define T_     400
#define U_     64
#define E_     320
#define INNER_ 512
#define VOCAB_ 1024

// ---------------------------------------------------------------------------
// Device-global scratch (no runtime allocation allowed)
// ---------------------------------------------------------------------------
__device__ float  g_encp[B_ * T_ * INNER_];   // enc @ W1[:, :E]
__device__ float  g_decp[B_ * U_ * INNER_];   // dec @ W1[:, E:] + b1
__device__ __half g_w2f[VOCAB_ * INNER_];     // W2 in fp16 (rn)

__device__ __forceinline__ float tanh_approx(float x) {
    float y; asm("tanh.approx.f32 %0, %1;" : "=f"(y) : "f"(x)); return y;
}

// ---------------------------------------------------------------------------
// Kernel 1: projection GEMM (unchanged, passing)
// ---------------------------------------------------------------------------
__global__ __launch_bounds__(256)
void proj_kernel(const float* __restrict__ A, const float* __restrict__ W1,
                 const float* __restrict__ b1, int isDec)
{
    __shared__ float As[16][64];
    __shared__ float Ws[16][68];

    const int tid  = threadIdx.x;
    const int m0   = blockIdx.x * 64;
    const int n0   = blockIdx.y * 64;
    const int koff = isDec ? E_ : 0;

    float acc[4][4] = {};

    for (int k0 = 0; k0 < E_; k0 += 16) {
        #pragma unroll
        for (int i = tid; i < 64 * 16; i += 256) {
            int r = i >> 4, k = i & 15;
            As[k][r] = A[(m0 + r) * E_ + k0 + k];
        }
        #pragma unroll
        for (int i = tid; i < 64 * 16; i += 256) {
            int c = i >> 4, k = i & 15;
            Ws[k][c] = W1[(n0 + c) * (2 * E_) + koff + k0 + k];
        }
        __syncthreads();

        const int ty = tid >> 4, tx = tid & 15;
        #pragma unroll
        for (int k = 0; k < 16; k++) {
            float a[4], w[4];
            #pragma unroll
            for (int i = 0; i < 4; i++) a[i] = As[k][ty * 4 + i];
            #pragma unroll
            for (int j = 0; j < 4; j++) w[j] = Ws[k][tx * 4 + j];
            #pragma unroll
            for (int i = 0; i < 4; i++)
                #pragma unroll
                for (int j = 0; j < 4; j++)
                    acc[i][j] = fmaf(a[i], w[j], acc[i][j]);
        }
        __syncthreads();
    }

    const int ty = tid >> 4, tx = tid & 15;
    float* C = isDec ? g_decp : g_encp;
    #pragma unroll
    for (int i = 0; i < 4; i++)
        #pragma unroll
        for (int j = 0; j < 4; j++) {
            float v = acc[i][j];
            if (isDec) v += b1[n0 + tx * 4 + j];
            C[(m0 + ty * 4 + i) * INNER_ + n0 + tx * 4 + j] = v;
        }
}

// ---------------------------------------------------------------------------
// Kernel 2: W2 fp32 -> fp16 (one-time)
// ---------------------------------------------------------------------------
__global__ __launch_bounds__(256)
void w2half_kernel(const float* __restrict__ W2)
{
    int i = blockIdx.x * 256 + threadIdx.x;
    if (i < VOCAB_ * INNER_) g_w2f[i] = __float2half_rn(W2[i]);
}

// ---------------------------------------------------------------------------
// Kernel 3: fused mma.sync kernel.
//   Block tile: 128 rows (16t x 8u) x 256 vocab, K-chunks of 64 (8 chunks).
//   8 warps in 2(m) x 4(n): each warp 64x64 via m16n8k16 fp16->f32
//   (32 MMAs per 32 fragment LDS.32 per k-step -> 1.0 MMA/LDS, was 0.67).
//   Rows padded to 72 fp16 (36 words, 36%32=4) -> all fragment LDS
//   conflict-free (banks 4g+lq cover 0..31).
//   tanh stage uses float4 es/ds loads (broadcast; 4x fewer wavefronts).
// ---------------------------------------------------------------------------
#define APAD 72

// dynamic smem layout (bytes)
#define O_ES    0                              // float[16][68]  4352
#define O_DS    4352                           // float[8][68]   2176
#define O_BIAS  6528                           // float[256]     1024
#define O_ASH   7552                           // half[128][72]  18432
#define O_BSH   25984                          // half[256][72]  36864
#define SMEM_SZ 62848

__global__ __launch_bounds__(256, 1)
void main_mma_kernel(const float* __restrict__ b2, float* __restrict__ out)
{
    extern __shared__ __align__(16) char smem[];
    float* es      = (float*)(smem + O_ES);      // [16][68]
    float* ds      = (float*)(smem + O_DS);      // [8][68]
    float* bias_s  = (float*)(smem + O_BIAS);    // [256]
    __half* Ash    = (__half*)(smem + O_ASH);    // [128][APAD]
    __half* Bsh    = (__half*)(smem + O_BSH);    // [256][APAD]

    const int tid  = threadIdx.x;
    const int wid  = tid >> 5;
    const int lane = tid & 31;

    const int b  = blockIdx.z;
    const int t0 = (blockIdx.y >> 3) * 16;
    const int u0 = (blockIdx.y & 7) * 8;
    const int v0 = blockIdx.x * 256;

    const int warp_m = wid >> 2;          // 0..1 : rows warp_m*64
    const int warp_n = wid & 3;           // 0..3 : cols warp_n*64

    const float* eb = g_encp + (b * T_ + t0) * INNER_;
    const float* db = g_decp + (b * U_ + u0) * INNER_;

    bias_s[tid] = b2[v0 + tid];

    float acc[4][8][4] = {};              // [mtile16][ntile8][4]

    const int g   = lane >> 2;            // 0..7
    const int lq  = lane & 3;             // 0..3
    const int klo = lq * 2;

    for (int c = 0; c < 8; c++) {
        __syncthreads();   // previous chunk's MMA reads done before overwrite

        // ---- stage proj chunks (fp32) ----
        {
            int r = tid >> 4, k = (tid & 15) * 4;
            float4 v = *(const float4*)(eb + r * INNER_ + c * 64 + k);
            *(float4*)&es[r * 68 + k] = v;
            if (tid < 128) {
                int r2 = tid >> 4, k2 = (tid & 15) * 4;
                float4 w = *(const float4*)(db + r2 * INNER_ + c * 64 + k2);
                *(float4*)&ds[r2 * 68 + k2] = w;
            }
        }
        // ---- stage B tile: 256 v x 64 k fp16 ----
        {
            #pragma unroll
            for (int it = 0; it < 8; it++) {
                int idx = it * 256 + tid;
                int v   = idx >> 3;
                int seg = idx & 7;
                uint4 x = *(const uint4*)(g_w2f + (size_t)(v0 + v) * INNER_ + c * 64 + seg * 8);
                *(uint4*)&Bsh[v * APAD + seg * 8] = x;
            }
        }
        __syncthreads();

        // ---- build h tile: tanh(enc+dec) -> fp16 (float4 es/ds loads) ----
        {
            int r  = tid >> 1;            // 0..127
            int kh = (tid & 1) * 32;
            int tt = r >> 3, uu = r & 7;
            const float* ep = &es[tt * 68 + kh];
            const float* dp = &ds[uu * 68 + kh];
            #pragma unroll
            for (int k4 = 0; k4 < 32; k4 += 4) {
                float4 ev = *(const float4*)(ep + k4);
                float4 dv = *(const float4*)(dp + k4);
                float h0 = tanh_approx(ev.x + dv.x);
                float h1 = tanh_approx(ev.y + dv.y);
                float h2 = tanh_approx(ev.z + dv.z);
                float h3 = tanh_approx(ev.w + dv.w);
                __half2 p0 = __floats2half2_rn(h0, h1);
                __half2 p1 = __floats2half2_rn(h2, h3);
                uint2 pk;
                pk.x = *reinterpret_cast<uint32_t*>(&p0);
                pk.y = *reinterpret_cast<uint32_t*>(&p1);
                *(uint2*)&Ash[r * APAD + kh + k4] = pk;
            }
        }
        __syncthreads();

        // ---- MMA: 4 k-steps of 16, warp tile 64x64 ----
        #pragma unroll
        for (int ks = 0; ks < 4; ks++) {
            const int kb = ks * 16;
            uint32_t af[4][4];
            #pragma unroll
            for (int mt = 0; mt < 4; mt++) {
                const int rb = warp_m * 64 + mt * 16;
                af[mt][0] = *(const uint32_t*)&Ash[(rb + g    ) * APAD + kb + klo    ];
                af[mt][1] = *(const uint32_t*)&Ash[(rb + g + 8) * APAD + kb + klo    ];
                af[mt][2] = *(const uint32_t*)&Ash[(rb + g    ) * APAD + kb + klo + 8];
                af[mt][3] = *(const uint32_t*)&Ash[(rb + g + 8) * APAD + kb + klo + 8];
            }
            #pragma unroll
            for (int nt = 0; nt < 8; nt++) {
                const int nb = warp_n * 64 + nt * 8;
                uint32_t bf0 = *(const uint32_t*)&Bsh[(nb + g) * APAD + kb + klo    ];
                uint32_t bf1 = *(const uint32_t*)&Bsh[(nb + g) * APAD + kb + klo + 8];
                #pragma unroll
                for (int mt = 0; mt < 4; mt++) {
                    asm volatile(
                        "mma.sync.aligned.m16n8k16.row.col.f32.f16.f16.f32 "
                        "{%0,%1,%2,%3}, {%4,%5,%6,%7}, {%8,%9}, {%0,%1,%2,%3};"
                        : "+f"(acc[mt][nt][0]), "+f"(acc[mt][nt][1]),
                          "+f"(acc[mt][nt][2]), "+f"(acc[mt][nt][3])
                        : "r"(af[mt][0]), "r"(af[mt][1]), "r"(af[mt][2]), "r"(af[mt][3]),
                          "r"(bf0), "r"(bf1));
                }
            }
        }
    }
    __syncthreads();

    // ---- epilogue: +bias, store fp32 ----
    #pragma unroll
    for (int mt = 0; mt < 4; mt++) {
        const int rb = warp_m * 64 + mt * 16;
        #pragma unroll
        for (int half = 0; half < 2; half++) {
            const int r  = rb + g + half * 8;
            const int tt = r >> 3, uu = r & 7;
            float* op = out + ((size_t)((b * T_ + t0 + tt) * U_ + u0 + uu)) * VOCAB_ + v0;
            #pragma unroll
            for (int nt = 0; nt < 8; nt++) {
                const int col = warp_n * 64 + nt * 8 + klo;
                float2 s;
                s.x = acc[mt][nt][half * 2 + 0] + bias_s[col + 0];
                s.y = acc[mt][nt][half * 2 + 1] + bias_s[col + 1];
                *(float2*)(op + col) = s;
            }
        }
    }
}

// ---------------------------------------------------------------------------
extern "C" void kernel_launch(void* const* d_in, const int* in_sizes, int n_in,
                              void* d_out, int out_size)
{
    const float* enc = (const float*)d_in[0];   // (4,400,320)
    const float* dec = (const float*)d_in[1];   // (4,64,320)
    const float* W1  = (const float*)d_in[2];   // (512,640)
    const float* b1  = (const float*)d_in[3];   // (512,)
    const float* W2  = (const float*)d_in[4];   // (1024,512)
    const float* b2  = (const float*)d_in[5];   // (1024,)
    float* out = (float*)d_out;                 // (4,400,64,1024) f32

    proj_kernel<<<dim3(25, 8), 256>>>(enc, W1, b1, 0);
    proj_kernel<<<dim3(4, 8),  256>>>(dec, W1, b1, 1);
    w2half_kernel<<<(VOCAB_ * INNER_ + 255) / 256, 256>>>(W2);

    static int smem_set = 0;
    if (!smem_set) {
        cudaFuncSetAttribute(main_mma_kernel,
                             cudaFuncAttributeMaxDynamicSharedMemorySize, SMEM_SZ);
        smem_set = 1;
    }
    main_mma_kernel<<<dim3(4, 200, 4), 256, SMEM_SZ>>>(b2, out);
}